// round 5
// baseline (speedup 1.0000x reference)
#include <cuda_runtime.h>
#include <cuda_bf16.h>
#include <cstdint>

// VectorQuantizer: inputs [8,2048,512] f32, embeddings [4096,512] f32
// outputs (concatenated f32): quantized [8*2048*512], loss [1], indices [8*2048] (as float)

#define N_ROWS   16384
#define DIM      512
#define K_CODES  4096
#define Q_ELEMS  (N_ROWS * DIM)

// -------- scratch (static device globals; no allocation) --------
__device__ float  g_xx[N_ROWS];    // ||x||^2 per input row
__device__ float  g_ee[K_CODES];   // ||e||^2 per code
__device__ int    g_idx[N_ROWS];   // argmin index per row
__device__ double g_part[N_ROWS];  // per-row loss partial sums

// -------- packed f32x2 helpers (FFMA2 path, sm_103a) --------
__device__ __forceinline__ unsigned long long pack2(float lo, float hi) {
    unsigned long long r;
    asm("mov.b64 %0, {%1, %2};" : "=l"(r) : "r"(__float_as_uint(lo)), "r"(__float_as_uint(hi)));
    return r;
}
__device__ __forceinline__ void unpack2(unsigned long long p, float& lo, float& hi) {
    unsigned int a, b;
    asm("mov.b64 {%0, %1}, %2;" : "=r"(a), "=r"(b) : "l"(p));
    lo = __uint_as_float(a); hi = __uint_as_float(b);
}
__device__ __forceinline__ unsigned long long ffma2(unsigned long long a, unsigned long long b,
                                                    unsigned long long c) {
    unsigned long long d;
    asm("fma.rn.f32x2 %0, %1, %2, %3;" : "=l"(d) : "l"(a), "l"(b), "l"(c));
    return d;
}

// ============================================================
// Kernel 1: squared row norms of X (16384 rows) and E (4096 rows).
// One warp per row. Pattern mirrors the XLA-GPU row-reduce:
// float4 loads strided by warp, sequential x/y/z/w per thread,
// butterfly tree reduction.
// ============================================================
__global__ void norms_kernel(const float* __restrict__ X, const float* __restrict__ E) {
    int w    = (blockIdx.x * blockDim.x + threadIdx.x) >> 5;
    int lane = threadIdx.x & 31;

    const float* src;
    float* dst;
    if (w < N_ROWS) {
        src = X + (size_t)w * DIM;
        dst = &g_xx[w];
    } else if (w < N_ROWS + K_CODES) {
        src = E + (size_t)(w - N_ROWS) * DIM;
        dst = &g_ee[w - N_ROWS];
    } else {
        return;
    }

    const float4* p = (const float4*)src;
    float acc = 0.0f;
#pragma unroll
    for (int i = 0; i < 4; i++) {
        float4 v = p[lane + 32 * i];
        acc += v.x * v.x;
        acc += v.y * v.y;
        acc += v.z * v.z;
        acc += v.w * v.w;
    }
#pragma unroll
    for (int o = 16; o > 0; o >>= 1)
        acc += __shfl_xor_sync(0xffffffffu, acc, o);
    if (lane == 0) *dst = acc;
}

// ============================================================
// Kernel 2: fused distance-GEMM + argmin.
// Block tile: 64 rows x 128 codes, looped over all 4096 codes.
// Thread tile: 4 rows x 8 codes, packed f32x2 accumulators (FFMA2).
// B fragments read from smem directly as ulonglong2 (consecutive code
// pairs == packed f32x2 operands; zero repack cost).
// Distance replicates reference rounding: fl(fl(xx+ee) - fl(2*dot)).
// Tie-break: lowest code index (jnp.argmin first-occurrence).
// ============================================================
#define BM 64
#define BN 128
#define KB 16
#define TM 4
#define TN 8

__global__ __launch_bounds__(256, 2)
void argmin_kernel(const float* __restrict__ X, const float* __restrict__ E) {
    __shared__ float As[2][KB][BM];
    __shared__ float Bs[2][KB][BN];
    __shared__ float Ees[BN];
    __shared__ float sm_v[BM][16];
    __shared__ int   sm_i[BM][16];

    const int tid = threadIdx.x;
    const int tx  = tid & 15;   // code group (0..15) -> 8 codes
    const int ty  = tid >> 4;   // row group  (0..15) -> 4 rows
    const int r0  = blockIdx.x * BM;

    float xr[TM];
#pragma unroll
    for (int r = 0; r < TM; r++) xr[r] = g_xx[r0 + ty * TM + r];

    float bestv[TM];
    int   besti[TM];
#pragma unroll
    for (int r = 0; r < TM; r++) { bestv[r] = 3.4e38f; besti[r] = 0; }

    // A loader: 64x16 floats = 256 float4, 1 per thread
    const int a_i = tid >> 2;        // row within tile
    const int a_j = tid & 3;         // float4 column within 16-wide chunk

    for (int ct = 0; ct < K_CODES / BN; ct++) {
        const int c0 = ct * BN;
        if (tid < BN) Ees[tid] = g_ee[c0 + tid];

        unsigned long long acc[TM][TN / 2];
#pragma unroll
        for (int r = 0; r < TM; r++)
#pragma unroll
            for (int p = 0; p < TN / 2; p++) acc[r][p] = 0ull;

        // prologue: chunk 0 -> buffer 0
        {
            float4 va = *(const float4*)(X + (size_t)(r0 + a_i) * DIM + a_j * 4);
            As[0][a_j * 4 + 0][a_i] = va.x;
            As[0][a_j * 4 + 1][a_i] = va.y;
            As[0][a_j * 4 + 2][a_i] = va.z;
            As[0][a_j * 4 + 3][a_i] = va.w;
#pragma unroll
            for (int l = 0; l < 2; l++) {
                int idx = tid + l * 256;
                int bi = idx >> 2, bj = idx & 3;
                float4 vb = *(const float4*)(E + (size_t)(c0 + bi) * DIM + bj * 4);
                Bs[0][bj * 4 + 0][bi] = vb.x;
                Bs[0][bj * 4 + 1][bi] = vb.y;
                Bs[0][bj * 4 + 2][bi] = vb.z;
                Bs[0][bj * 4 + 3][bi] = vb.w;
            }
        }
        __syncthreads();

        int buf = 0;
        for (int kc = 0; kc < DIM / KB; kc++) {
            const int nbuf = buf ^ 1;
            if (kc + 1 < DIM / KB) {
                const int kb = (kc + 1) * KB;
                float4 va = *(const float4*)(X + (size_t)(r0 + a_i) * DIM + kb + a_j * 4);
                As[nbuf][a_j * 4 + 0][a_i] = va.x;
                As[nbuf][a_j * 4 + 1][a_i] = va.y;
                As[nbuf][a_j * 4 + 2][a_i] = va.z;
                As[nbuf][a_j * 4 + 3][a_i] = va.w;
#pragma unroll
                for (int l = 0; l < 2; l++) {
                    int idx = tid + l * 256;
                    int bi = idx >> 2, bj = idx & 3;
                    float4 vb = *(const float4*)(E + (size_t)(c0 + bi) * DIM + kb + bj * 4);
                    Bs[nbuf][bj * 4 + 0][bi] = vb.x;
                    Bs[nbuf][bj * 4 + 1][bi] = vb.y;
                    Bs[nbuf][bj * 4 + 2][bi] = vb.z;
                    Bs[nbuf][bj * 4 + 3][bi] = vb.w;
                }
            }
#pragma unroll
            for (int kk = 0; kk < KB; kk++) {
                float4 a = *(const float4*)&As[buf][kk][ty * TM];
                ulonglong2 bq0 = *(const ulonglong2*)&Bs[buf][kk][tx * TN];
                ulonglong2 bq1 = *(const ulonglong2*)&Bs[buf][kk][tx * TN + 4];
                unsigned long long bp[4] = {bq0.x, bq0.y, bq1.x, bq1.y};
                float av[TM] = {a.x, a.y, a.z, a.w};
#pragma unroll
                for (int r = 0; r < TM; r++) {
                    unsigned long long ap = pack2(av[r], av[r]);
#pragma unroll
                    for (int p = 0; p < 4; p++)
                        acc[r][p] = ffma2(ap, bp[p], acc[r][p]);
                }
            }
            __syncthreads();
            buf = nbuf;
        }

        // epilogue: distances + running argmin (ascending code order -> '<' keeps first min)
        float ev[TN];
#pragma unroll
        for (int p = 0; p < TN; p++) ev[p] = Ees[tx * TN + p];
#pragma unroll
        for (int r = 0; r < TM; r++) {
#pragma unroll
            for (int p = 0; p < 4; p++) {
                float d0, d1;
                unpack2(acc[r][p], d0, d1);
                const int cc = c0 + tx * TN + p * 2;
                float dist0 = __fsub_rn(__fadd_rn(xr[r], ev[p * 2]),     __fmul_rn(2.0f, d0));
                float dist1 = __fsub_rn(__fadd_rn(xr[r], ev[p * 2 + 1]), __fmul_rn(2.0f, d1));
                if (dist0 < bestv[r]) { bestv[r] = dist0; besti[r] = cc; }
                if (dist1 < bestv[r]) { bestv[r] = dist1; besti[r] = cc + 1; }
            }
        }
        __syncthreads();  // protect Ees / smem reuse across code tiles
    }

    // cross-thread argmin reduce (16 candidates per row), tie -> lowest index
#pragma unroll
    for (int r = 0; r < TM; r++) {
        sm_v[ty * TM + r][tx] = bestv[r];
        sm_i[ty * TM + r][tx] = besti[r];
    }
    __syncthreads();
    if (tid < BM) {
        float bv = sm_v[tid][0];
        int   bi = sm_i[tid][0];
#pragma unroll
        for (int t = 1; t < 16; t++) {
            float v = sm_v[tid][t];
            int   i = sm_i[tid][t];
            if (v < bv || (v == bv && i < bi)) { bv = v; bi = i; }
        }
        g_idx[r0 + tid] = bi;
    }
}

// ============================================================
// Kernel 3: gather + straight-through output + loss partials + indices.
// out = fl(x + fl(q - x)) matches reference bit pattern.
// ============================================================
__global__ void gather_kernel(const float* __restrict__ X, const float* __restrict__ E,
                              float* __restrict__ out, int write_tail) {
    __shared__ double sm[4];
    const int row = blockIdx.x;
    const int t   = threadIdx.x;     // 128 threads, one float4 each
    const int idx = g_idx[row];

    const float4 xv = ((const float4*)(X + (size_t)row * DIM))[t];
    const float4 ev = ((const float4*)(E + (size_t)idx * DIM))[t];

    float4 ov;
    double s = 0.0;
    float d;
    d = __fsub_rn(ev.x, xv.x); ov.x = __fadd_rn(xv.x, d); s += (double)d * (double)d;
    d = __fsub_rn(ev.y, xv.y); ov.y = __fadd_rn(xv.y, d); s += (double)d * (double)d;
    d = __fsub_rn(ev.z, xv.z); ov.z = __fadd_rn(xv.z, d); s += (double)d * (double)d;
    d = __fsub_rn(ev.w, xv.w); ov.w = __fadd_rn(xv.w, d); s += (double)d * (double)d;

    ((float4*)(out + (size_t)row * DIM))[t] = ov;

    // deterministic block reduce: warp butterfly + sequential across 4 warps
#pragma unroll
    for (int o = 16; o > 0; o >>= 1)
        s += __shfl_xor_sync(0xffffffffu, s, o);
    if ((t & 31) == 0) sm[t >> 5] = s;
    __syncthreads();
    if (t == 0) {
        double tot = sm[0] + sm[1] + sm[2] + sm[3];
        g_part[row] = tot;
        if (write_tail) out[Q_ELEMS + 1 + row] = (float)idx;
    }
}

// ============================================================
// Kernel 4: final loss reduction (fixed order, deterministic).
// loss = fl(m + fl(0.25f * m)), m = mse (q_latent == e_latent numerically).
// ============================================================
__global__ void loss_kernel(float* __restrict__ out, int write_tail) {
    __shared__ double sm[256];
    const int t = threadIdx.x;
    double s = 0.0;
    for (int i = t; i < N_ROWS; i += 256) s += g_part[i];
    sm[t] = s;
    __syncthreads();
#pragma unroll
    for (int o = 128; o > 0; o >>= 1) {
        if (t < o) sm[t] += sm[t + o];
        __syncthreads();
    }
    if (t == 0 && write_tail) {
        float m = (float)(sm[0] / (double)Q_ELEMS);
        out[Q_ELEMS] = __fadd_rn(m, __fmul_rn(0.25f, m));
    }
}

// ============================================================
extern "C" void kernel_launch(void* const* d_in, const int* in_sizes, int n_in,
                              void* d_out, int out_size) {
    const float* X = (const float*)d_in[0];
    const float* E = (const float*)d_in[1];
    // defensive: identify tensors by size if order differs
    if (n_in >= 2 && in_sizes[0] == K_CODES * DIM && in_sizes[1] == N_ROWS * DIM) {
        const float* tmp = X; X = E; E = tmp;
    }
    float* out = (float*)d_out;
    const int write_tail = (out_size >= Q_ELEMS + 1 + N_ROWS) ? 1 : 0;

    // 1) norms: (16384 + 4096) warps
    {
        int warps = N_ROWS + K_CODES;
        int blocks = (warps * 32 + 255) / 256;
        norms_kernel<<<blocks, 256>>>(X, E);
    }
    // 2) distance GEMM + argmin
    argmin_kernel<<<N_ROWS / BM, 256>>>(X, E);
    // 3) gather + STE + loss partials + indices
    gather_kernel<<<N_ROWS, 128>>>(X, E, out, write_tail);
    // 4) loss
    loss_kernel<<<1, 256>>>(out, write_tail);
}

// round 8
// speedup vs baseline: 1.6854x; 1.6854x over previous
#include <cuda_runtime.h>
#include <cuda_bf16.h>
#include <cstdint>

// VectorQuantizer: inputs [8,2048,512] f32, embeddings [4096,512] f32
// outputs (concatenated f32): quantized [8*2048*512], loss [1], indices [8*2048] (as float)

#define N_ROWS   16384
#define DIM      512
#define K_CODES  4096
#define Q_ELEMS  (N_ROWS * DIM)

// -------- scratch (static device globals; no allocation) --------
__device__ float  g_xx[N_ROWS];    // ||x||^2 per input row
__device__ float  g_ee[K_CODES];   // ||e||^2 per code
__device__ int    g_idx[N_ROWS];   // argmin index per row
__device__ double g_part[N_ROWS];  // per-row loss partial sums

// ============================================================
// Kernel 1: squared row norms of X (16384 rows) and E (4096 rows).
// One warp per row; float4 strided loads; butterfly reduction.
// (Validated: produced exact index match in Round-5 pass.)
// ============================================================
__global__ void norms_kernel(const float* __restrict__ X, const float* __restrict__ E) {
    int w    = (blockIdx.x * blockDim.x + threadIdx.x) >> 5;
    int lane = threadIdx.x & 31;

    const float* src;
    float* dst;
    if (w < N_ROWS) {
        src = X + (size_t)w * DIM;
        dst = &g_xx[w];
    } else if (w < N_ROWS + K_CODES) {
        src = E + (size_t)(w - N_ROWS) * DIM;
        dst = &g_ee[w - N_ROWS];
    } else {
        return;
    }

    const float4* p = (const float4*)src;
    float acc = 0.0f;
#pragma unroll
    for (int i = 0; i < 4; i++) {
        float4 v = p[lane + 32 * i];
        acc += v.x * v.x;
        acc += v.y * v.y;
        acc += v.z * v.z;
        acc += v.w * v.w;
    }
#pragma unroll
    for (int o = 16; o > 0; o >>= 1)
        acc += __shfl_xor_sync(0xffffffffu, acc, o);
    if (lane == 0) *dst = acc;
}

// ============================================================
// Kernel 2: fused distance-GEMM + argmin — SCALAR FFMA inner loop.
// Block tile: 64 rows x 128 codes, looped over all 4096 codes.
// Thread tile: 4 rows x 8 codes, plain float accumulators.
// (A/B vs Round-5 pass: dropped f32x2/u64 path — suspected register-pairing
//  MOV bloat / spills caused the 4x perf gap; f32x2 also sits at the smem
//  crossbar bound anyway. Numerically identical: same accumulation order,
//  same epilogue rounding, same tie-break.)
// ============================================================
#define BM 64
#define BN 128
#define KB 16
#define TM 4
#define TN 8

__global__ __launch_bounds__(256, 2)
void argmin_kernel(const float* __restrict__ X, const float* __restrict__ E) {
    __shared__ float As[2][KB][BM];
    __shared__ float Bs[2][KB][BN];
    __shared__ float Ees[BN];
    __shared__ float sm_v[BM][16];
    __shared__ int   sm_i[BM][16];

    const int tid = threadIdx.x;
    const int tx  = tid & 15;   // code group (0..15) -> 8 codes
    const int ty  = tid >> 4;   // row group  (0..15) -> 4 rows
    const int r0  = blockIdx.x * BM;

    float xr[TM];
#pragma unroll
    for (int r = 0; r < TM; r++) xr[r] = g_xx[r0 + ty * TM + r];

    float bestv[TM];
    int   besti[TM];
#pragma unroll
    for (int r = 0; r < TM; r++) { bestv[r] = 3.4e38f; besti[r] = 0; }

    // A loader: 64x16 floats = 256 float4, 1 per thread
    const int a_i = tid >> 2;        // row within tile
    const int a_j = tid & 3;         // float4 column within 16-wide chunk

    for (int ct = 0; ct < K_CODES / BN; ct++) {
        const int c0 = ct * BN;
        if (tid < BN) Ees[tid] = g_ee[c0 + tid];

        float acc[TM][TN];
#pragma unroll
        for (int r = 0; r < TM; r++)
#pragma unroll
            for (int n = 0; n < TN; n++) acc[r][n] = 0.0f;

        // prologue: chunk 0 -> buffer 0
        {
            float4 va = *(const float4*)(X + (size_t)(r0 + a_i) * DIM + a_j * 4);
            As[0][a_j * 4 + 0][a_i] = va.x;
            As[0][a_j * 4 + 1][a_i] = va.y;
            As[0][a_j * 4 + 2][a_i] = va.z;
            As[0][a_j * 4 + 3][a_i] = va.w;
#pragma unroll
            for (int l = 0; l < 2; l++) {
                int idx = tid + l * 256;
                int bi = idx >> 2, bj = idx & 3;
                float4 vb = *(const float4*)(E + (size_t)(c0 + bi) * DIM + bj * 4);
                Bs[0][bj * 4 + 0][bi] = vb.x;
                Bs[0][bj * 4 + 1][bi] = vb.y;
                Bs[0][bj * 4 + 2][bi] = vb.z;
                Bs[0][bj * 4 + 3][bi] = vb.w;
            }
        }
        __syncthreads();

        int buf = 0;
        for (int kc = 0; kc < DIM / KB; kc++) {
            const int nbuf = buf ^ 1;
            if (kc + 1 < DIM / KB) {
                const int kb = (kc + 1) * KB;
                float4 va = *(const float4*)(X + (size_t)(r0 + a_i) * DIM + kb + a_j * 4);
                As[nbuf][a_j * 4 + 0][a_i] = va.x;
                As[nbuf][a_j * 4 + 1][a_i] = va.y;
                As[nbuf][a_j * 4 + 2][a_i] = va.z;
                As[nbuf][a_j * 4 + 3][a_i] = va.w;
#pragma unroll
                for (int l = 0; l < 2; l++) {
                    int idx = tid + l * 256;
                    int bi = idx >> 2, bj = idx & 3;
                    float4 vb = *(const float4*)(E + (size_t)(c0 + bi) * DIM + kb + bj * 4);
                    Bs[nbuf][bj * 4 + 0][bi] = vb.x;
                    Bs[nbuf][bj * 4 + 1][bi] = vb.y;
                    Bs[nbuf][bj * 4 + 2][bi] = vb.z;
                    Bs[nbuf][bj * 4 + 3][bi] = vb.w;
                }
            }
#pragma unroll
            for (int kk = 0; kk < KB; kk++) {
                const float4 a  = *(const float4*)&As[buf][kk][ty * TM];
                const float4 b0 = *(const float4*)&Bs[buf][kk][tx * TN];
                const float4 b1 = *(const float4*)&Bs[buf][kk][tx * TN + 4];
                const float av[TM] = {a.x, a.y, a.z, a.w};
                const float bv[TN] = {b0.x, b0.y, b0.z, b0.w, b1.x, b1.y, b1.z, b1.w};
#pragma unroll
                for (int r = 0; r < TM; r++)
#pragma unroll
                    for (int n = 0; n < TN; n++)
                        acc[r][n] = __fmaf_rn(av[r], bv[n], acc[r][n]);
            }
            __syncthreads();
            buf = nbuf;
        }

        // epilogue: distances + running argmin (ascending code order -> '<' keeps first min)
        float ev[TN];
#pragma unroll
        for (int n = 0; n < TN; n++) ev[n] = Ees[tx * TN + n];
#pragma unroll
        for (int r = 0; r < TM; r++) {
#pragma unroll
            for (int n = 0; n < TN; n++) {
                const int cc = c0 + tx * TN + n;
                float dist = __fsub_rn(__fadd_rn(xr[r], ev[n]), __fmul_rn(2.0f, acc[r][n]));
                if (dist < bestv[r]) { bestv[r] = dist; besti[r] = cc; }
            }
        }
        __syncthreads();  // protect Ees / smem reuse across code tiles
    }

    // cross-thread argmin reduce (16 candidates per row), tie -> lowest index
#pragma unroll
    for (int r = 0; r < TM; r++) {
        sm_v[ty * TM + r][tx] = bestv[r];
        sm_i[ty * TM + r][tx] = besti[r];
    }
    __syncthreads();
    if (tid < BM) {
        float bv = sm_v[tid][0];
        int   bi = sm_i[tid][0];
#pragma unroll
        for (int t = 1; t < 16; t++) {
            float v = sm_v[tid][t];
            int   i = sm_i[tid][t];
            if (v < bv || (v == bv && i < bi)) { bv = v; bi = i; }
        }
        g_idx[r0 + tid] = bi;
    }
}

// ============================================================
// Kernel 3: gather + straight-through output + loss partials + indices.
// out = fl(x + fl(q - x)) matches reference bit pattern.
// ============================================================
__global__ void gather_kernel(const float* __restrict__ X, const float* __restrict__ E,
                              float* __restrict__ out, int write_tail) {
    __shared__ double sm[4];
    const int row = blockIdx.x;
    const int t   = threadIdx.x;     // 128 threads, one float4 each
    const int idx = g_idx[row];

    const float4 xv = ((const float4*)(X + (size_t)row * DIM))[t];
    const float4 ev = ((const float4*)(E + (size_t)idx * DIM))[t];

    float4 ov;
    double s = 0.0;
    float d;
    d = __fsub_rn(ev.x, xv.x); ov.x = __fadd_rn(xv.x, d); s += (double)d * (double)d;
    d = __fsub_rn(ev.y, xv.y); ov.y = __fadd_rn(xv.y, d); s += (double)d * (double)d;
    d = __fsub_rn(ev.z, xv.z); ov.z = __fadd_rn(xv.z, d); s += (double)d * (double)d;
    d = __fsub_rn(ev.w, xv.w); ov.w = __fadd_rn(xv.w, d); s += (double)d * (double)d;

    ((float4*)(out + (size_t)row * DIM))[t] = ov;

    // deterministic block reduce: warp butterfly + sequential across 4 warps
#pragma unroll
    for (int o = 16; o > 0; o >>= 1)
        s += __shfl_xor_sync(0xffffffffu, s, o);
    if ((t & 31) == 0) sm[t >> 5] = s;
    __syncthreads();
    if (t == 0) {
        double tot = sm[0] + sm[1] + sm[2] + sm[3];
        g_part[row] = tot;
        if (write_tail) out[Q_ELEMS + 1 + row] = (float)idx;
    }
}

// ============================================================
// Kernel 4: final loss reduction (fixed order, deterministic).
// loss = fl(m + fl(0.25f * m)), m = mse.
// ============================================================
__global__ void loss_kernel(float* __restrict__ out, int write_tail) {
    __shared__ double sm[256];
    const int t = threadIdx.x;
    double s = 0.0;
    for (int i = t; i < N_ROWS; i += 256) s += g_part[i];
    sm[t] = s;
    __syncthreads();
#pragma unroll
    for (int o = 128; o > 0; o >>= 1) {
        if (t < o) sm[t] += sm[t + o];
        __syncthreads();
    }
    if (t == 0 && write_tail) {
        float m = (float)(sm[0] / (double)Q_ELEMS);
        out[Q_ELEMS] = __fadd_rn(m, __fmul_rn(0.25f, m));
    }
}

// ============================================================
extern "C" void kernel_launch(void* const* d_in, const int* in_sizes, int n_in,
                              void* d_out, int out_size) {
    const float* X = (const float*)d_in[0];
    const float* E = (const float*)d_in[1];
    // defensive: identify tensors by size if order differs
    if (n_in >= 2 && in_sizes[0] == K_CODES * DIM && in_sizes[1] == N_ROWS * DIM) {
        const float* tmp = X; X = E; E = tmp;
    }
    float* out = (float*)d_out;
    const int write_tail = (out_size >= Q_ELEMS + 1 + N_ROWS) ? 1 : 0;

    // 1) norms: (16384 + 4096) warps
    {
        int warps = N_ROWS + K_CODES;
        int blocks = (warps * 32 + 255) / 256;
        norms_kernel<<<blocks, 256>>>(X, E);
    }
    // 2) distance GEMM + argmin
    argmin_kernel<<<N_ROWS / BM, 256>>>(X, E);
    // 3) gather + STE + loss partials + indices
    gather_kernel<<<N_ROWS, 128>>>(X, E, out, write_tail);
    // 4) loss
    loss_kernel<<<1, 256>>>(out, write_tail);
}